// round 9
// baseline (speedup 1.0000x reference)
#include <cuda_runtime.h>
#include <cstdint>

// DynamicGRU: B=32, T=2048, D=256, N=256
// Phase 1: PRE = x @ [W_g[:256,:] | W_c[:256,:]] + bias  (f32x2 GEMM)
// Phase 2: persistent scan, 4-CTA cluster per batch row, register-resident
//          recurrent weights, DSMEM broadcast with release/acquire flag
//          handshake (no cluster.sync in the loop).

#define BATCH_ 32
#define T_     2048

__device__ float g_pre[(size_t)BATCH_ * T_ * 768];

// ---------------------------------------------------------------------------
// shared helpers
// ---------------------------------------------------------------------------
__device__ __forceinline__ uint32_t smem_u32_(const void* p) {
    uint32_t a;
    asm("{ .reg .u64 t; cvta.to.shared.u64 t, %1; cvt.u32.u64 %0, t; }"
        : "=r"(a) : "l"(p));
    return a;
}
__device__ __forceinline__ uint64_t pack2_(float a, float b) {
    uint64_t r;
    asm("mov.b64 %0, {%1, %2};" : "=l"(r) : "f"(a), "f"(b));
    return r;
}
__device__ __forceinline__ void unpack2_(uint64_t v, float& a, float& b) {
    asm("mov.b64 {%0, %1}, %2;" : "=f"(a), "=f"(b) : "l"(v));
}
__device__ __forceinline__ void fma2_(uint64_t& d, uint64_t a, uint64_t b) {
    asm("fma.rn.f32x2 %0, %1, %2, %0;" : "+l"(d) : "l"(a), "l"(b));
}
__device__ __forceinline__ void lds_v2u64_(uint32_t addr, uint64_t& a, uint64_t& b) {
    asm volatile("ld.shared.v2.u64 {%0, %1}, [%2];" : "=l"(a), "=l"(b) : "r"(addr));
}

// ---------------------------------------------------------------------------
// Phase 1: f32x2 GEMM  [65536,256] x [256,768] -> g_pre (bias folded).
// BM=128, BN=128, BK=16, 256 threads, 8x8 thread tile, FFMA2 MACs.
// ---------------------------------------------------------------------------
__global__ __launch_bounds__(256) void gemm_pre_kernel(
    const float* __restrict__ x,
    const float* __restrict__ Wg, const float* __restrict__ bg,
    const float* __restrict__ Wc, const float* __restrict__ bc)
{
    __shared__ __align__(16) float As[16 * 132];   // [k][m]
    __shared__ __align__(16) float Bs[16 * 128];   // [k][n]

    const int bn  = blockIdx.x;   // 0..5 (128-wide col block)
    const int bm  = blockIdx.y;   // 0..511
    const int tid = threadIdx.x;

    const float* Wp; int ldw, coff; const float* bias;
    if (bn < 4) { Wp = Wg; ldw = 512; coff = bn * 128;       bias = bg + coff; }
    else        { Wp = Wc; ldw = 256; coff = (bn - 4) * 128; bias = bc + coff; }

    const int tx   = tid & 15;          // col group (8 cols)
    const int ty   = tid >> 4;          // row group (8 rows)
    const int arow = tid >> 2;          // 0..63
    const int acol = (tid & 3) * 4;     // 0,4,8,12
    const int brow = tid >> 4;          // 0..15
    const int bcol = (tid & 15) * 8;    // 0..120

    const float* Ag = x + (size_t)(bm * 128) * 256;
    const uint32_t bs_u32 = smem_u32_(Bs) + tx * 32;

    uint64_t acc[8][4];
#pragma unroll
    for (int i = 0; i < 8; ++i)
#pragma unroll
        for (int j = 0; j < 4; ++j) acc[i][j] = 0ull;

    for (int kt = 0; kt < 256; kt += 16) {
        float4 a0 = *(const float4*)(Ag + (size_t)arow * 256 + kt + acol);
        float4 a1 = *(const float4*)(Ag + (size_t)(arow + 64) * 256 + kt + acol);
        float4 b0 = *(const float4*)(Wp + (size_t)(kt + brow) * ldw + coff + bcol);
        float4 b1 = *(const float4*)(Wp + (size_t)(kt + brow) * ldw + coff + bcol + 4);

        As[(acol + 0) * 132 + arow]      = a0.x;
        As[(acol + 1) * 132 + arow]      = a0.y;
        As[(acol + 2) * 132 + arow]      = a0.z;
        As[(acol + 3) * 132 + arow]      = a0.w;
        As[(acol + 0) * 132 + arow + 64] = a1.x;
        As[(acol + 1) * 132 + arow + 64] = a1.y;
        As[(acol + 2) * 132 + arow + 64] = a1.z;
        As[(acol + 3) * 132 + arow + 64] = a1.w;
        *(float4*)&Bs[brow * 128 + bcol]     = b0;
        *(float4*)&Bs[brow * 128 + bcol + 4] = b1;
        __syncthreads();

#pragma unroll
        for (int k = 0; k < 16; ++k) {
            float4 av0 = *(const float4*)&As[k * 132 + ty * 8];
            float4 av1 = *(const float4*)&As[k * 132 + ty * 8 + 4];
            uint64_t b01, b23, b45, b67;
            lds_v2u64_(bs_u32 + k * 512,      b01, b23);
            lds_v2u64_(bs_u32 + k * 512 + 16, b45, b67);
            float am[8] = {av0.x, av0.y, av0.z, av0.w,
                           av1.x, av1.y, av1.z, av1.w};
#pragma unroll
            for (int i = 0; i < 8; ++i) {
                uint64_t ad = pack2_(am[i], am[i]);
                fma2_(acc[i][0], ad, b01);
                fma2_(acc[i][1], ad, b23);
                fma2_(acc[i][2], ad, b45);
                fma2_(acc[i][3], ad, b67);
            }
        }
        __syncthreads();
    }

    float4 bb0 = *(const float4*)(bias + tx * 8);
    float4 bb1 = *(const float4*)(bias + tx * 8 + 4);
    float* Og = g_pre + (size_t)(bm * 128) * 768 + bn * 128;
#pragma unroll
    for (int i = 0; i < 8; ++i) {
        float o0, o1, o2, o3, o4, o5, o6, o7;
        unpack2_(acc[i][0], o0, o1);
        unpack2_(acc[i][1], o2, o3);
        unpack2_(acc[i][2], o4, o5);
        unpack2_(acc[i][3], o6, o7);
        float4 r0 = make_float4(o0 + bb0.x, o1 + bb0.y, o2 + bb0.z, o3 + bb0.w);
        float4 r1 = make_float4(o4 + bb1.x, o5 + bb1.y, o6 + bb1.z, o7 + bb1.w);
        float* dst = Og + (size_t)(ty * 8 + i) * 768 + tx * 8;
        *(float4*)dst       = r0;
        *(float4*)(dst + 4) = r1;
    }
}

// ---------------------------------------------------------------------------
// Phase 2 cluster helpers
// ---------------------------------------------------------------------------
__device__ __forceinline__ void cluster_sync_() {
    asm volatile("barrier.cluster.arrive.aligned;" ::: "memory");
    asm volatile("barrier.cluster.wait.aligned;" ::: "memory");
}
__device__ __forceinline__ uint32_t mapa_(uint32_t laddr, int rk) {
    uint32_t ra;
    asm("mapa.shared::cluster.u32 %0, %1, %2;" : "=r"(ra) : "r"(laddr), "r"(rk));
    return ra;
}
__device__ __forceinline__ void st_cluster_f32_(uint32_t raddr, float v) {
    asm volatile("st.shared::cluster.f32 [%0], %1;" :: "r"(raddr), "f"(v) : "memory");
}
__device__ __forceinline__ void st_release_s32_(uint32_t raddr, int v) {
    asm volatile("st.release.cluster.shared::cluster.b32 [%0], %1;"
                 :: "r"(raddr), "r"(v) : "memory");
}
__device__ __forceinline__ int ld_acquire_s32_(uint32_t laddr) {
    int v;
    asm volatile("ld.acquire.cluster.shared::cta.b32 %0, [%1];"
                 : "=r"(v) : "r"(laddr) : "memory");
    return v;
}
__device__ __forceinline__ void bar64_(int id) {
    asm volatile("bar.sync %0, 64;" :: "r"(id) : "memory");
}

// ---------------------------------------------------------------------------
// Phase 2: grid = 128 CTAs, cluster(4,1,1), 512 threads. Warp w: gate slice
// sg=w&3 (64 k), gate cols (w>>2)*32+lane; cand slice sc=w&7 (32 k), cand
// cols (w>>3)*32+lane. Weights register-resident.
// ---------------------------------------------------------------------------
__global__ void __cluster_dims__(4, 1, 1) __launch_bounds__(512, 1)
gru_rec_kernel(const float* __restrict__ Wg, const float* __restrict__ Wc,
               const float* __restrict__ h0, float* __restrict__ out)
{
    __shared__ __align__(16) float hbuf[256];
    __shared__ __align__(16) float rhbuf[256];
    __shared__ float ubuf[64];
    __shared__ float pbuf[2 * 192];
    __shared__ __align__(16) float redA[128 * 4];   // [col][slice]
    __shared__ __align__(16) float redB[64 * 8];    // [col][slice]
    __shared__ int rh_flag[4];
    __shared__ int h_flag[4];

    const int tid  = threadIdx.x;
    const int w    = tid >> 5;
    const int lane = tid & 31;
    uint32_t rank;
    asm("mov.u32 %0, %%cluster_ctarank;" : "=r"(rank));
    const int b = blockIdx.x >> 2;

    const int sg  = w & 3;
    const int col = (w >> 2) * 32 + lane;          // 0..127
    const int gcol = (col < 64) ? (int)(rank * 64 + col)
                                : (int)(256 + rank * 64 + (col - 64));
    const int sc  = w & 7;
    const int cc  = (w >> 3) * 32 + lane;          // 0..63
    const int ccol = rank * 64 + cc;

    // register-resident weights
    uint64_t wg2[32];
#pragma unroll
    for (int j = 0; j < 16; ++j) {
        int k = sg * 64 + j * 4;
        float w0 = Wg[(size_t)(256 + k + 0) * 512 + gcol];
        float w1 = Wg[(size_t)(256 + k + 1) * 512 + gcol];
        float w2 = Wg[(size_t)(256 + k + 2) * 512 + gcol];
        float w3 = Wg[(size_t)(256 + k + 3) * 512 + gcol];
        wg2[2 * j]     = pack2_(w0, w1);
        wg2[2 * j + 1] = pack2_(w2, w3);
    }
    uint64_t wc2[16];
#pragma unroll
    for (int j = 0; j < 8; ++j) {
        int k = sc * 32 + j * 4;
        float w0 = Wc[(size_t)(256 + k + 0) * 256 + ccol];
        float w1 = Wc[(size_t)(256 + k + 1) * 256 + ccol];
        float w2 = Wc[(size_t)(256 + k + 2) * 256 + ccol];
        float w3 = Wc[(size_t)(256 + k + 3) * 256 + ccol];
        wc2[2 * j]     = pack2_(w0, w1);
        wc2[2 * j + 1] = pack2_(w2, w3);
    }

    for (int i = tid; i < 256; i += 512) hbuf[i] = h0[b * 256 + i];
    if (tid < 4) { rh_flag[tid] = 0; h_flag[tid] = 0; }

    int preidx = 0;
    if      (tid < 64)  preidx = rank * 64 + tid;
    else if (tid < 128) preidx = 256 + rank * 64 + (tid - 64);
    else if (tid < 192) preidx = 512 + rank * 64 + (tid - 128);

    const float* prow = g_pre + (size_t)b * T_ * 768;
    float*       orow = out   + (size_t)b * T_ * 256;

    if (tid < 192) pbuf[tid] = prow[preidx];
    __syncthreads();
    cluster_sync_();   // flags initialized cluster-wide; hbuf local ready

    const uint32_t hb   = smem_u32_(hbuf);
    const uint32_t rhb  = smem_u32_(rhbuf);
    const uint32_t ha_g = hb  + sg * 256;
    const uint32_t ra_c = rhb + sc * 128;
    const uint32_t rhf_l = smem_u32_(rh_flag);
    const uint32_t hf_l  = smem_u32_(h_flag);

    // remote data addresses (tid<64 writers)
    uint32_t rh_rem[4], h_rem[4];
    {
        uint32_t my_rh = rhb + (rank * 64 + (tid & 63)) * 4;
        uint32_t my_h  = hb  + (rank * 64 + (tid & 63)) * 4;
#pragma unroll
        for (int rk = 0; rk < 4; ++rk) {
            rh_rem[rk] = mapa_(my_rh, rk);
            h_rem[rk]  = mapa_(my_h,  rk);
        }
    }
    // remote flag addresses (tid==0)
    uint32_t rhf_rem[4], hf_rem[4];
#pragma unroll
    for (int rk = 0; rk < 4; ++rk) {
        rhf_rem[rk] = mapa_(rhf_l + rank * 4, rk);
        hf_rem[rk]  = mapa_(hf_l  + rank * 4, rk);
    }

    for (int t = 0; t < T_; ++t) {
        const int cur = (t & 1) * 192, nxt = ((t & 1) ^ 1) * 192;
        const int tgt = t + 1;

        float pre_next = 0.f;
        if (tid < 192 && t + 1 < T_)
            pre_next = prow[(size_t)(t + 1) * 768 + preidx];

        // ---- gates partial: h[sg*64..+64) . wg ----
        {
            uint64_t a0 = 0, a1 = 0;
#pragma unroll
            for (int j = 0; j < 16; ++j) {
                uint64_t h01, h23;
                lds_v2u64_(ha_g + j * 16, h01, h23);
                fma2_(a0, wg2[2 * j],     h01);
                fma2_(a1, wg2[2 * j + 1], h23);
            }
            float x0, x1, y0, y1;
            unpack2_(a0, x0, x1);
            unpack2_(a1, y0, y1);
            redA[col * 4 + sg] = (x0 + x1) + (y0 + y1);
        }
        __syncthreads();

        // ---- gate finalize ----
        if (tid < 128) {
            float4 p4 = *(const float4*)&redA[tid * 4];
            float s = p4.x + p4.y + p4.z + p4.w + pbuf[cur + tid];
            float g = 1.f / (1.f + __expf(-s));
            if (tid < 64) {
                float rh = g * hbuf[rank * 64 + tid];
#pragma unroll
                for (int rk = 0; rk < 4; ++rk) st_cluster_f32_(rh_rem[rk], rh);
            } else {
                ubuf[tid - 64] = g;
            }
        }
        if (tid < 64) {
            bar64_(1);
            if (tid == 0) {
#pragma unroll
                for (int rk = 0; rk < 4; ++rk) st_release_s32_(rhf_rem[rk], tgt);
            }
        }
        // wait rh cluster-wide
#pragma unroll
        for (int r = 0; r < 4; ++r)
            while (ld_acquire_s32_(rhf_l + r * 4) < tgt) {}

        // ---- candidate partial: rh[sc*32..+32) . wc ----
        {
            uint64_t c0 = 0, c1 = 0;
#pragma unroll
            for (int j = 0; j < 8; ++j) {
                uint64_t h01, h23;
                lds_v2u64_(ra_c + j * 16, h01, h23);
                fma2_(c0, wc2[2 * j],     h01);
                fma2_(c1, wc2[2 * j + 1], h23);
            }
            float x0, x1, y0, y1;
            unpack2_(c0, x0, x1);
            unpack2_(c1, y0, y1);
            redB[cc * 8 + sc] = (x0 + x1) + (y0 + y1);
        }
        __syncthreads();

        // ---- h update ----
        if (tid < 64) {
            float4 p0 = *(const float4*)&redB[tid * 8];
            float4 p1 = *(const float4*)&redB[tid * 8 + 4];
            float s = ((p0.x + p0.y) + (p0.z + p0.w))
                    + ((p1.x + p1.y) + (p1.z + p1.w))
                    + pbuf[cur + 128 + tid];
            float c  = tanhf(s);
            float u  = ubuf[tid];
            float hn = u * hbuf[rank * 64 + tid] + (1.f - u) * c;
            orow[(size_t)t * 256 + rank * 64 + tid] = hn;
#pragma unroll
            for (int rk = 0; rk < 4; ++rk) st_cluster_f32_(h_rem[rk], hn);
            bar64_(2);
            if (tid == 0) {
#pragma unroll
                for (int rk = 0; rk < 4; ++rk) st_release_s32_(hf_rem[rk], tgt);
            }
        }
        if (tid < 192) pbuf[nxt + tid] = pre_next;
        // wait h cluster-wide
#pragma unroll
        for (int r = 0; r < 4; ++r)
            while (ld_acquire_s32_(hf_l + r * 4) < tgt) {}
    }
}

// ---------------------------------------------------------------------------
extern "C" void kernel_launch(void* const* d_in, const int* in_sizes, int n_in,
                              void* d_out, int out_size) {
    const float* x  = (const float*)d_in[0];
    const float* h0 = (const float*)d_in[1];
    const float* Wg = (const float*)d_in[2];
    const float* bg = (const float*)d_in[3];
    const float* Wc = (const float*)d_in[4];
    const float* bc = (const float*)d_in[5];
    float* out = (float*)d_out;

    dim3 g1(6, 512);
    gemm_pre_kernel<<<g1, 256>>>(x, Wg, bg, Wc, bc);
    gru_rec_kernel<<<128, 512>>>(Wg, Wc, h0, out);
}

// round 10
// speedup vs baseline: 1.1079x; 1.1079x over previous
#include <cuda_runtime.h>
#include <cstdint>

// DynamicGRU: B=32, T=2048, D=256, N=256
// Phase 1: PRE = x @ [W_g[:256,:] | W_c[:256,:]] + bias  (parallel GEMM)
// Phase 2: persistent scan, 4-CTA cluster per batch row, register-resident
//          recurrent weights, DSMEM broadcast + mbarrier handshake
//          (no cluster.sync, no flag spinning in the loop).

#define BATCH_ 32
#define T_     2048

__device__ float g_pre[(size_t)BATCH_ * T_ * 768];

// ---------------------------------------------------------------------------
// Phase 1: fp32 tiled GEMM  [65536,256] x [256,768] -> g_pre (bias folded).
// BM=128, BN=64, BK=16, 256 threads, 8x4 register tile.  (R8 version, 504us)
// ---------------------------------------------------------------------------
__global__ __launch_bounds__(256) void gemm_pre_kernel(
    const float* __restrict__ x,
    const float* __restrict__ Wg, const float* __restrict__ bg,
    const float* __restrict__ Wc, const float* __restrict__ bc)
{
    __shared__ float As[16 * 132];
    __shared__ float Bs[16 * 64];

    const int bn  = blockIdx.x;
    const int bm  = blockIdx.y;
    const int tid = threadIdx.x;

    const float* Wp; int ldw, coff; const float* bias;
    if (bn < 8) { Wp = Wg; ldw = 512; coff = bn * 64;        bias = bg + coff; }
    else        { Wp = Wc; ldw = 256; coff = (bn - 8) * 64;  bias = bc + coff; }

    const int tx   = tid & 15;
    const int ty   = tid >> 4;
    const int arow = tid >> 2;
    const int acol = (tid & 3) * 4;
    const int brow = tid >> 4;
    const int bcol = (tid & 15) * 4;

    const float* Ag = x + (size_t)(bm * 128) * 256;

    float acc[8][4];
#pragma unroll
    for (int i = 0; i < 8; ++i)
#pragma unroll
        for (int j = 0; j < 4; ++j) acc[i][j] = 0.f;

    for (int kt = 0; kt < 256; kt += 16) {
        float4 a0 = *(const float4*)(Ag + (size_t)arow * 256 + kt + acol);
        float4 a1 = *(const float4*)(Ag + (size_t)(arow + 64) * 256 + kt + acol);
        float4 b0 = *(const float4*)(Wp + (size_t)(kt + brow) * ldw + coff + bcol);

        As[(acol + 0) * 132 + arow]      = a0.x;
        As[(acol + 1) * 132 + arow]      = a0.y;
        As[(acol + 2) * 132 + arow]      = a0.z;
        As[(acol + 3) * 132 + arow]      = a0.w;
        As[(acol + 0) * 132 + arow + 64] = a1.x;
        As[(acol + 1) * 132 + arow + 64] = a1.y;
        As[(acol + 2) * 132 + arow + 64] = a1.z;
        As[(acol + 3) * 132 + arow + 64] = a1.w;
        *(float4*)&Bs[brow * 64 + bcol] = b0;
        __syncthreads();

#pragma unroll
        for (int k = 0; k < 16; ++k) {
            float4 av0 = *(const float4*)&As[k * 132 + ty * 8];
            float4 av1 = *(const float4*)&As[k * 132 + ty * 8 + 4];
            float4 bv  = *(const float4*)&Bs[k * 64 + tx * 4];
            float am[8] = {av0.x, av0.y, av0.z, av0.w,
                           av1.x, av1.y, av1.z, av1.w};
#pragma unroll
            for (int i = 0; i < 8; ++i) {
                acc[i][0] += am[i] * bv.x;
                acc[i][1] += am[i] * bv.y;
                acc[i][2] += am[i] * bv.z;
                acc[i][3] += am[i] * bv.w;
            }
        }
        __syncthreads();
    }

    float4 bb = *(const float4*)(bias + tx * 4);
    float* Og = g_pre + (size_t)(bm * 128) * 768 + bn * 64;
#pragma unroll
    for (int i = 0; i < 8; ++i) {
        float4 o;
        o.x = acc[i][0] + bb.x;
        o.y = acc[i][1] + bb.y;
        o.z = acc[i][2] + bb.z;
        o.w = acc[i][3] + bb.w;
        *(float4*)(Og + (size_t)(ty * 8 + i) * 768 + tx * 4) = o;
    }
}

// ---------------------------------------------------------------------------
// Phase 2 helpers
// ---------------------------------------------------------------------------
__device__ __forceinline__ void cluster_sync_() {
    asm volatile("barrier.cluster.arrive.aligned;" ::: "memory");
    asm volatile("barrier.cluster.wait.aligned;" ::: "memory");
}
__device__ __forceinline__ uint32_t smem_u32_(const void* p) {
    uint32_t a;
    asm("{ .reg .u64 t; cvta.to.shared.u64 t, %1; cvt.u32.u64 %0, t; }"
        : "=r"(a) : "l"(p));
    return a;
}
__device__ __forceinline__ uint32_t mapa_(uint32_t laddr, int rk) {
    uint32_t ra;
    asm("mapa.shared::cluster.u32 %0, %1, %2;" : "=r"(ra) : "r"(laddr), "r"(rk));
    return ra;
}
__device__ __forceinline__ void st_cluster_f32_(uint32_t raddr, float v) {
    asm volatile("st.shared::cluster.f32 [%0], %1;" :: "r"(raddr), "f"(v) : "memory");
}
__device__ __forceinline__ void mbar_init_(uint32_t laddr, uint32_t cnt) {
    asm volatile("mbarrier.init.shared.b64 [%0], %1;" :: "r"(laddr), "r"(cnt) : "memory");
}
__device__ __forceinline__ void mbar_arrive_rel_cluster_(uint32_t raddr) {
    asm volatile("mbarrier.arrive.release.cluster.shared::cluster.b64 _, [%0];"
                 :: "r"(raddr) : "memory");
}
__device__ __forceinline__ void mbar_wait_acq_cluster_(uint32_t laddr, uint32_t parity) {
    asm volatile(
        "{\n\t.reg .pred P;\n\t"
        "WL%=:\n\t"
        "mbarrier.try_wait.parity.acquire.cluster.shared::cta.b64 P, [%0], %1, 0x989680;\n\t"
        "@P bra.uni WD%=;\n\t"
        "bra.uni WL%=;\n\t"
        "WD%=:\n\t}"
        :: "r"(laddr), "r"(parity) : "memory");
}
__device__ __forceinline__ uint64_t pack2_(float a, float b) {
    uint64_t r;
    asm("mov.b64 %0, {%1, %2};" : "=l"(r) : "f"(a), "f"(b));
    return r;
}
__device__ __forceinline__ void unpack2_(uint64_t v, float& a, float& b) {
    asm("mov.b64 {%0, %1}, %2;" : "=f"(a), "=f"(b) : "l"(v));
}
__device__ __forceinline__ void fma2_(uint64_t& d, uint64_t a, uint64_t b) {
    asm("fma.rn.f32x2 %0, %1, %2, %0;" : "+l"(d) : "l"(a), "l"(b));
}
__device__ __forceinline__ void lds_v2u64_(uint32_t addr, uint64_t& a, uint64_t& b) {
    asm volatile("ld.shared.v2.u64 {%0, %1}, [%2];" : "=l"(a), "=l"(b) : "r"(addr));
}

// ---------------------------------------------------------------------------
// Phase 2: grid = 128 CTAs, cluster(4,1,1), 512 threads. Warp w: gate slice
// sg=w&3 (64 k), gate cols (w>>2)*32+lane; cand slice sc=w&7 (32 k), cand
// cols (w>>3)*32+lane. Weights register-resident. mbarrier handshake:
// mbar_rh / mbar_h, count = 256 (64 producers x 4 source CTAs).
// ---------------------------------------------------------------------------
__global__ void __cluster_dims__(4, 1, 1) __launch_bounds__(512, 1)
gru_rec_kernel(const float* __restrict__ Wg, const float* __restrict__ Wc,
               const float* __restrict__ h0, float* __restrict__ out)
{
    __shared__ __align__(16) float hbuf[256];
    __shared__ __align__(16) float rhbuf[256];
    __shared__ float ubuf[64];
    __shared__ float pbuf[2 * 192];
    __shared__ __align__(16) float redA[128 * 4];   // [col][slice]
    __shared__ __align__(16) float redB[64 * 8];    // [col][slice]
    __shared__ __align__(8) uint64_t mbar_rh;
    __shared__ __align__(8) uint64_t mbar_h;

    const int tid  = threadIdx.x;
    const int w    = tid >> 5;
    const int lane = tid & 31;
    uint32_t rank;
    asm("mov.u32 %0, %%cluster_ctarank;" : "=r"(rank));
    const int b = blockIdx.x >> 2;

    const int sg  = w & 3;
    const int col = (w >> 2) * 32 + lane;          // 0..127
    const int gcol = (col < 64) ? (int)(rank * 64 + col)
                                : (int)(256 + rank * 64 + (col - 64));
    const int sc  = w & 7;
    const int cc  = (w >> 3) * 32 + lane;          // 0..63
    const int ccol = rank * 64 + cc;

    // register-resident weights
    uint64_t wg2[32];
#pragma unroll
    for (int j = 0; j < 16; ++j) {
        int k = sg * 64 + j * 4;
        float w0 = Wg[(size_t)(256 + k + 0) * 512 + gcol];
        float w1 = Wg[(size_t)(256 + k + 1) * 512 + gcol];
        float w2 = Wg[(size_t)(256 + k + 2) * 512 + gcol];
        float w3 = Wg[(size_t)(256 + k + 3) * 512 + gcol];
        wg2[2 * j]     = pack2_(w0, w1);
        wg2[2 * j + 1] = pack2_(w2, w3);
    }
    uint64_t wc2[16];
#pragma unroll
    for (int j = 0; j < 8; ++j) {
        int k = sc * 32 + j * 4;
        float w0 = Wc[(size_t)(256 + k + 0) * 256 + ccol];
        float w1 = Wc[(size_t)(256 + k + 1) * 256 + ccol];
        float w2 = Wc[(size_t)(256 + k + 2) * 256 + ccol];
        float w3 = Wc[(size_t)(256 + k + 3) * 256 + ccol];
        wc2[2 * j]     = pack2_(w0, w1);
        wc2[2 * j + 1] = pack2_(w2, w3);
    }

    for (int i = tid; i < 256; i += 512) hbuf[i] = h0[b * 256 + i];

    const uint32_t mrh_l = smem_u32_(&mbar_rh);
    const uint32_t mh_l  = smem_u32_(&mbar_h);
    if (tid == 0) {
        mbar_init_(mrh_l, 256);
        mbar_init_(mh_l, 256);
    }

    int preidx = 0;
    if      (tid < 64)  preidx = rank * 64 + tid;
    else if (tid < 128) preidx = 256 + rank * 64 + (tid - 64);
    else if (tid < 192) preidx = 512 + rank * 64 + (tid - 128);

    const float* prow = g_pre + (size_t)b * T_ * 768;
    float*       orow = out   + (size_t)b * T_ * 256;

    if (tid < 192) pbuf[tid] = prow[preidx];
    __syncthreads();
    cluster_sync_();   // mbar init + hbuf visible cluster-wide

    const uint32_t hb   = smem_u32_(hbuf);
    const uint32_t rhb  = smem_u32_(rhbuf);
    const uint32_t ha_g = hb  + sg * 256;
    const uint32_t ra_c = rhb + sc * 128;

    // remote data + barrier addresses (producers tid<64)
    uint32_t rh_rem[4], h_rem[4], mrh_rem[4], mh_rem[4];
    {
        uint32_t my_rh = rhb + (rank * 64 + (tid & 63)) * 4;
        uint32_t my_h  = hb  + (rank * 64 + (tid & 63)) * 4;
#pragma unroll
        for (int rk = 0; rk < 4; ++rk) {
            rh_rem[rk]  = mapa_(my_rh, rk);
            h_rem[rk]   = mapa_(my_h,  rk);
            mrh_rem[rk] = mapa_(mrh_l, rk);
            mh_rem[rk]  = mapa_(mh_l,  rk);
        }
    }

    for (int t = 0; t < T_; ++t) {
        const int cur = (t & 1) * 192, nxt = ((t & 1) ^ 1) * 192;
        const uint32_t par = (uint32_t)(t & 1);

        float pre_next = 0.f;
        if (tid < 192 && t + 1 < T_)
            pre_next = prow[(size_t)(t + 1) * 768 + preidx];

        // ---- gates partial: h[sg*64..+64) . wg ----
        {
            uint64_t a0 = 0, a1 = 0;
#pragma unroll
            for (int j = 0; j < 16; ++j) {
                uint64_t h01, h23;
                lds_v2u64_(ha_g + j * 16, h01, h23);
                fma2_(a0, wg2[2 * j],     h01);
                fma2_(a1, wg2[2 * j + 1], h23);
            }
            float x0, x1, y0, y1;
            unpack2_(a0, x0, x1);
            unpack2_(a1, y0, y1);
            redA[col * 4 + sg] = (x0 + x1) + (y0 + y1);
        }
        __syncthreads();

        // ---- gate finalize: 128 threads, one column each ----
        if (tid < 128) {
            float4 p4 = *(const float4*)&redA[tid * 4];
            float s = p4.x + p4.y + p4.z + p4.w + pbuf[cur + tid];
            float g = 1.f / (1.f + __expf(-s));
            if (tid < 64) {
                float rh = g * hbuf[rank * 64 + tid];
#pragma unroll
                for (int rk = 0; rk < 4; ++rk) st_cluster_f32_(rh_rem[rk], rh);
#pragma unroll
                for (int rk = 0; rk < 4; ++rk) mbar_arrive_rel_cluster_(mrh_rem[rk]);
            } else {
                ubuf[tid - 64] = g;
            }
        }
        mbar_wait_acq_cluster_(mrh_l, par);   // rhbuf complete cluster-wide

        // ---- candidate partial: rh[sc*32..+32) . wc ----
        {
            uint64_t c0 = 0, c1 = 0;
#pragma unroll
            for (int j = 0; j < 8; ++j) {
                uint64_t h01, h23;
                lds_v2u64_(ra_c + j * 16, h01, h23);
                fma2_(c0, wc2[2 * j],     h01);
                fma2_(c1, wc2[2 * j + 1], h23);
            }
            float x0, x1, y0, y1;
            unpack2_(c0, x0, x1);
            unpack2_(c1, y0, y1);
            redB[cc * 8 + sc] = (x0 + x1) + (y0 + y1);
        }
        __syncthreads();

        // ---- h update: 64 threads, one column each ----
        if (tid < 64) {
            float4 p0 = *(const float4*)&redB[tid * 8];
            float4 p1 = *(const float4*)&redB[tid * 8 + 4];
            float s = ((p0.x + p0.y) + (p0.z + p0.w))
                    + ((p1.x + p1.y) + (p1.z + p1.w))
                    + pbuf[cur + 128 + tid];
            float c  = tanhf(s);
            float u  = ubuf[tid];
            float hn = u * hbuf[rank * 64 + tid] + (1.f - u) * c;
            orow[(size_t)t * 256 + rank * 64 + tid] = hn;
#pragma unroll
            for (int rk = 0; rk < 4; ++rk) st_cluster_f32_(h_rem[rk], hn);
#pragma unroll
            for (int rk = 0; rk < 4; ++rk) mbar_arrive_rel_cluster_(mh_rem[rk]);
        }
        if (tid < 192) pbuf[nxt + tid] = pre_next;
        mbar_wait_acq_cluster_(mh_l, par);    // hbuf complete cluster-wide
    }
}

// ---------------------------------------------------------------------------
extern "C" void kernel_launch(void* const* d_in, const int* in_sizes, int n_in,
                              void* d_out, int out_size) {
    const float* x  = (const float*)d_in[0];
    const float* h0 = (const float*)d_in[1];
    const float* Wg = (const float*)d_in[2];
    const float* bg = (const float*)d_in[3];
    const float* Wc = (const float*)d_in[4];
    const float* bc = (const float*)d_in[5];
    float* out = (float*)d_out;

    dim3 g1(12, 512);
    gemm_pre_kernel<<<g1, 256>>>(x, Wg, bg, Wc, bc);
    gru_rec_kernel<<<128, 512>>>(Wg, Wc, h0, out);
}

// round 11
// speedup vs baseline: 1.7584x; 1.5872x over previous
#include <cuda_runtime.h>
#include <cstdint>

// DynamicGRU: B=32, T=2048, D=256, N=256
// Phase 1: PRE = x @ [W_g[:256,:] | W_c[:256,:]] + bias  (parallel GEMM)
// Phase 2: persistent scan, 4-CTA cluster per batch row, register-resident
//          weights. Split r/u gate MACs; u-MAC hidden in the rh cluster-
//          barrier wait shadow (arrive/wait split); hbuf/rhbuf double-
//          buffered by step parity so the overlap is race-free.

#define BATCH_ 32
#define T_     2048

__device__ float g_pre[(size_t)BATCH_ * T_ * 768];

// ---------------------------------------------------------------------------
// Phase 1: fp32 tiled GEMM  [65536,256] x [256,768] -> g_pre (bias folded).
// BM=128, BN=64, BK=16, 256 threads, 8x4 register tile.  (R8 version)
// ---------------------------------------------------------------------------
__global__ __launch_bounds__(256) void gemm_pre_kernel(
    const float* __restrict__ x,
    const float* __restrict__ Wg, const float* __restrict__ bg,
    const float* __restrict__ Wc, const float* __restrict__ bc)
{
    __shared__ float As[16 * 132];
    __shared__ float Bs[16 * 64];

    const int bn  = blockIdx.x;
    const int bm  = blockIdx.y;
    const int tid = threadIdx.x;

    const float* Wp; int ldw, coff; const float* bias;
    if (bn < 8) { Wp = Wg; ldw = 512; coff = bn * 64;        bias = bg + coff; }
    else        { Wp = Wc; ldw = 256; coff = (bn - 8) * 64;  bias = bc + coff; }

    const int tx   = tid & 15;
    const int ty   = tid >> 4;
    const int arow = tid >> 2;
    const int acol = (tid & 3) * 4;
    const int brow = tid >> 4;
    const int bcol = (tid & 15) * 4;

    const float* Ag = x + (size_t)(bm * 128) * 256;

    float acc[8][4];
#pragma unroll
    for (int i = 0; i < 8; ++i)
#pragma unroll
        for (int j = 0; j < 4; ++j) acc[i][j] = 0.f;

    for (int kt = 0; kt < 256; kt += 16) {
        float4 a0 = *(const float4*)(Ag + (size_t)arow * 256 + kt + acol);
        float4 a1 = *(const float4*)(Ag + (size_t)(arow + 64) * 256 + kt + acol);
        float4 b0 = *(const float4*)(Wp + (size_t)(kt + brow) * ldw + coff + bcol);

        As[(acol + 0) * 132 + arow]      = a0.x;
        As[(acol + 1) * 132 + arow]      = a0.y;
        As[(acol + 2) * 132 + arow]      = a0.z;
        As[(acol + 3) * 132 + arow]      = a0.w;
        As[(acol + 0) * 132 + arow + 64] = a1.x;
        As[(acol + 1) * 132 + arow + 64] = a1.y;
        As[(acol + 2) * 132 + arow + 64] = a1.z;
        As[(acol + 3) * 132 + arow + 64] = a1.w;
        *(float4*)&Bs[brow * 64 + bcol] = b0;
        __syncthreads();

#pragma unroll
        for (int k = 0; k < 16; ++k) {
            float4 av0 = *(const float4*)&As[k * 132 + ty * 8];
            float4 av1 = *(const float4*)&As[k * 132 + ty * 8 + 4];
            float4 bv  = *(const float4*)&Bs[k * 64 + tx * 4];
            float am[8] = {av0.x, av0.y, av0.z, av0.w,
                           av1.x, av1.y, av1.z, av1.w};
#pragma unroll
            for (int i = 0; i < 8; ++i) {
                acc[i][0] += am[i] * bv.x;
                acc[i][1] += am[i] * bv.y;
                acc[i][2] += am[i] * bv.z;
                acc[i][3] += am[i] * bv.w;
            }
        }
        __syncthreads();
    }

    float4 bb = *(const float4*)(bias + tx * 4);
    float* Og = g_pre + (size_t)(bm * 128) * 768 + bn * 64;
#pragma unroll
    for (int i = 0; i < 8; ++i) {
        float4 o;
        o.x = acc[i][0] + bb.x;
        o.y = acc[i][1] + bb.y;
        o.z = acc[i][2] + bb.z;
        o.w = acc[i][3] + bb.w;
        *(float4*)(Og + (size_t)(ty * 8 + i) * 768 + tx * 4) = o;
    }
}

// ---------------------------------------------------------------------------
// Phase 2 helpers
// ---------------------------------------------------------------------------
__device__ __forceinline__ void cluster_sync_() {
    asm volatile("barrier.cluster.arrive.aligned;" ::: "memory");
    asm volatile("barrier.cluster.wait.aligned;" ::: "memory");
}
__device__ __forceinline__ void cluster_arrive_() {
    asm volatile("barrier.cluster.arrive.aligned;" ::: "memory");
}
__device__ __forceinline__ void cluster_wait_() {
    asm volatile("barrier.cluster.wait.aligned;" ::: "memory");
}
__device__ __forceinline__ uint32_t smem_u32_(const void* p) {
    uint32_t a;
    asm("{ .reg .u64 t; cvta.to.shared.u64 t, %1; cvt.u32.u64 %0, t; }"
        : "=r"(a) : "l"(p));
    return a;
}
__device__ __forceinline__ uint32_t mapa_(uint32_t laddr, int rk) {
    uint32_t ra;
    asm("mapa.shared::cluster.u32 %0, %1, %2;" : "=r"(ra) : "r"(laddr), "r"(rk));
    return ra;
}
__device__ __forceinline__ void st_cluster_f32_(uint32_t raddr, float v) {
    asm volatile("st.shared::cluster.f32 [%0], %1;" :: "r"(raddr), "f"(v) : "memory");
}
__device__ __forceinline__ uint64_t pack2_(float a, float b) {
    uint64_t r;
    asm("mov.b64 %0, {%1, %2};" : "=l"(r) : "f"(a), "f"(b));
    return r;
}
__device__ __forceinline__ void unpack2_(uint64_t v, float& a, float& b) {
    asm("mov.b64 {%0, %1}, %2;" : "=f"(a), "=f"(b) : "l"(v));
}
__device__ __forceinline__ void fma2_(uint64_t& d, uint64_t a, uint64_t b) {
    asm("fma.rn.f32x2 %0, %1, %2, %0;" : "+l"(d) : "l"(a), "l"(b));
}
__device__ __forceinline__ void lds_v2u64_(uint32_t addr, uint64_t& a, uint64_t& b) {
    asm volatile("ld.shared.v2.u64 {%0, %1}, [%2];" : "=l"(a), "=l"(b) : "r"(addr));
}

// ---------------------------------------------------------------------------
// Phase 2: grid = 128 CTAs, cluster(4,1,1), 512 threads, 16 warps.
// Warp w: k-slice s = w&7 (32 k values), col group g = w>>3 -> local col
// lc = g*32+lane (0..63). CTA rank owns global cols rank*64 + lc.
// Register weights: wr2/wu2/wc2 = 16 u64 each (96 regs total).
// ---------------------------------------------------------------------------
__global__ void __cluster_dims__(4, 1, 1) __launch_bounds__(512, 1)
gru_rec_kernel(const float* __restrict__ Wg, const float* __restrict__ Wc,
               const float* __restrict__ h0, float* __restrict__ out)
{
    __shared__ __align__(16) float hbuf[2][256];
    __shared__ __align__(16) float rhbuf[2][256];
    __shared__ float pbuf[2 * 192];
    __shared__ __align__(16) float redR[64 * 8];
    __shared__ __align__(16) float redU[64 * 8];
    __shared__ __align__(16) float redC[64 * 8];

    const int tid  = threadIdx.x;
    const int w    = tid >> 5;
    const int lane = tid & 31;
    uint32_t rank;
    asm("mov.u32 %0, %%cluster_ctarank;" : "=r"(rank));
    const int b = blockIdx.x >> 2;

    const int s  = w & 7;                 // k-slice (32 values)
    const int lc = (w >> 3) * 32 + lane;  // local col 0..63
    const int rcol = rank * 64 + lc;      // global r / cand col
    const int ucol = 256 + rcol;          // global u col

    // ---- register-resident weights ----
    uint64_t wr2[16], wu2[16], wc2[16];
#pragma unroll
    for (int j = 0; j < 8; ++j) {
        int k = s * 32 + j * 4;
        float r0 = Wg[(size_t)(256 + k + 0) * 512 + rcol];
        float r1 = Wg[(size_t)(256 + k + 1) * 512 + rcol];
        float r2 = Wg[(size_t)(256 + k + 2) * 512 + rcol];
        float r3 = Wg[(size_t)(256 + k + 3) * 512 + rcol];
        wr2[2 * j]     = pack2_(r0, r1);
        wr2[2 * j + 1] = pack2_(r2, r3);
        float u0 = Wg[(size_t)(256 + k + 0) * 512 + ucol];
        float u1 = Wg[(size_t)(256 + k + 1) * 512 + ucol];
        float u2 = Wg[(size_t)(256 + k + 2) * 512 + ucol];
        float u3 = Wg[(size_t)(256 + k + 3) * 512 + ucol];
        wu2[2 * j]     = pack2_(u0, u1);
        wu2[2 * j + 1] = pack2_(u2, u3);
        float c0 = Wc[(size_t)(256 + k + 0) * 256 + rcol];
        float c1 = Wc[(size_t)(256 + k + 1) * 256 + rcol];
        float c2 = Wc[(size_t)(256 + k + 2) * 256 + rcol];
        float c3 = Wc[(size_t)(256 + k + 3) * 256 + rcol];
        wc2[2 * j]     = pack2_(c0, c1);
        wc2[2 * j + 1] = pack2_(c2, c3);
    }

    for (int i = tid; i < 256; i += 512) {
        hbuf[0][i] = h0[b * 256 + i];
        hbuf[1][i] = 0.f;
    }

    int preidx = 0;
    if      (tid < 64)  preidx = rank * 64 + tid;                // r
    else if (tid < 128) preidx = 256 + rank * 64 + (tid - 64);   // u
    else if (tid < 192) preidx = 512 + rank * 64 + (tid - 128);  // c

    const float* prow = g_pre + (size_t)b * T_ * 768;
    float*       orow = out   + (size_t)b * T_ * 256;

    if (tid < 192) pbuf[tid] = prow[preidx];
    __syncthreads();
    cluster_sync_();   // hbuf[0] + pbuf visible; cluster aligned

    const uint32_t hb0  = smem_u32_(&hbuf[0][0]);
    const uint32_t rhb0 = smem_u32_(&rhbuf[0][0]);

    // per-warp MAC base addresses, both parities (k-slice offset = s*32 floats)
    const uint32_t ha[2]  = { hb0  + s * 128, hb0  + 1024 + s * 128 };
    const uint32_t ra[2]  = { rhb0 + s * 128, rhb0 + 1024 + s * 128 };

    // remote store addresses for producers (tid<64), both parities
    uint32_t rh_rem[2][4], h_rem[2][4];
    {
        uint32_t e = (rank * 64 + (tid & 63)) * 4;
#pragma unroll
        for (int rk = 0; rk < 4; ++rk) {
            rh_rem[0][rk] = mapa_(rhb0 + e, rk);
            rh_rem[1][rk] = mapa_(rhb0 + 1024 + e, rk);
            h_rem[0][rk]  = mapa_(hb0 + e, rk);
            h_rem[1][rk]  = mapa_(hb0 + 1024 + e, rk);
        }
    }

    for (int t = 0; t < T_; ++t) {
        const int par = t & 1, npar = par ^ 1;
        const int cur = par * 192, nxt = npar * 192;

        // prefetch next step's pre-activations (hidden behind this step)
        float pre_next = 0.f;
        if (tid < 192 && t + 1 < T_)
            pre_next = prow[(size_t)(t + 1) * 768 + preidx];

        // ---- r partial: h[par][s*32..+32) . wr  (all 16 warps, 64 cols) ----
        {
            uint64_t a0 = 0, a1 = 0;
#pragma unroll
            for (int j = 0; j < 8; ++j) {
                uint64_t h01, h23;
                lds_v2u64_(ha[par] + j * 16, h01, h23);
                fma2_(a0, wr2[2 * j],     h01);
                fma2_(a1, wr2[2 * j + 1], h23);
            }
            float x0, x1, y0, y1;
            unpack2_(a0, x0, x1);
            unpack2_(a1, y0, y1);
            redR[lc * 8 + s] = (x0 + x1) + (y0 + y1);
        }
        __syncthreads();

        // ---- r finalize + rh broadcast (tid<64) ----
        if (tid < 64) {
            float4 p0 = *(const float4*)&redR[tid * 8];
            float4 p1 = *(const float4*)&redR[tid * 8 + 4];
            float sm = ((p0.x + p0.y) + (p0.z + p0.w))
                     + ((p1.x + p1.y) + (p1.z + p1.w))
                     + pbuf[cur + tid];
            float r  = 1.f / (1.f + __expf(-sm));
            float rh = r * hbuf[par][rank * 64 + tid];
#pragma unroll
            for (int rk = 0; rk < 4; ++rk) st_cluster_f32_(rh_rem[par][rk], rh);
        }
        cluster_arrive_();   // release: rh stores ordered before arrive

        // ---- u partial (local hbuf only) -- runs in the wait shadow ----
        {
            uint64_t a0 = 0, a1 = 0;
#pragma unroll
            for (int j = 0; j < 8; ++j) {
                uint64_t h01, h23;
                lds_v2u64_(ha[par] + j * 16, h01, h23);
                fma2_(a0, wu2[2 * j],     h01);
                fma2_(a1, wu2[2 * j + 1], h23);
            }
            float x0, x1, y0, y1;
            unpack2_(a0, x0, x1);
            unpack2_(a1, y0, y1);
            redU[lc * 8 + s] = (x0 + x1) + (y0 + y1);
        }
        cluster_wait_();     // rhbuf[par] complete cluster-wide

        // ---- candidate partial: rh[par][s*32..+32) . wc ----
        {
            uint64_t c0 = 0, c1 = 0;
#pragma unroll
            for (int j = 0; j < 8; ++j) {
                uint64_t h01, h23;
                lds_v2u64_(ra[par] + j * 16, h01, h23);
                fma2_(c0, wc2[2 * j],     h01);
                fma2_(c1, wc2[2 * j + 1], h23);
            }
            float x0, x1, y0, y1;
            unpack2_(c0, x0, x1);
            unpack2_(c1, y0, y1);
            redC[lc * 8 + s] = (x0 + x1) + (y0 + y1);
        }
        __syncthreads();     // redU + redC ready

        // ---- h update (tid<64): u, c, h_new; broadcast h ----
        if (tid < 64) {
            float4 u0 = *(const float4*)&redU[tid * 8];
            float4 u1 = *(const float4*)&redU[tid * 8 + 4];
            float su = ((u0.x + u0.y) + (u0.z + u0.w))
                     + ((u1.x + u1.y) + (u1.z + u1.w))
                     + pbuf[cur + 64 + tid];
            float u = 1.f / (1.f + __expf(-su));

            float4 c0 = *(const float4*)&redC[tid * 8];
            float4 c1 = *(const float4*)&redC[tid * 8 + 4];
            float sc = ((c0.x + c0.y) + (c0.z + c0.w))
                     + ((c1.x + c1.y) + (c1.z + c1.w))
                     + pbuf[cur + 128 + tid];
            float c = tanhf(sc);

            float hn = u * hbuf[par][rank * 64 + tid] + (1.f - u) * c;
            orow[(size_t)t * 256 + rank * 64 + tid] = hn;
#pragma unroll
            for (int rk = 0; rk < 4; ++rk) st_cluster_f32_(h_rem[npar][rk], hn);
        }
        cluster_arrive_();   // release: h stores ordered before arrive
        if (tid < 192) pbuf[nxt + tid] = pre_next;   // wait shadow
        cluster_wait_();     // hbuf[npar] complete cluster-wide
    }
}

// ---------------------------------------------------------------------------
extern "C" void kernel_launch(void* const* d_in, const int* in_sizes, int n_in,
                              void* d_out, int out_size) {
    const float* x  = (const float*)d_in[0];
    const float* h0 = (const float*)d_in[1];
    const float* Wg = (const float*)d_in[2];
    const float* bg = (const float*)d_in[3];
    const float* Wc = (const float*)d_in[4];
    const float* bc = (const float*)d_in[5];
    float* out = (float*)d_out;

    dim3 g1(12, 512);
    gemm_pre_kernel<<<g1, 256>>>(x, Wg, bg, Wc, bc);
    gru_rec_kernel<<<128, 512>>>(Wg, Wc, h0, out);
}

// round 12
// speedup vs baseline: 2.1480x; 1.2215x over previous
#include <cuda_runtime.h>
#include <cstdint>

// DynamicGRU: B=32, T=2048, D=256, N=256
// Phase 1: PRE = x @ [W_g[:256,:] | W_c[:256,:]] + bias  (parallel GEMM)
// Phase 2: persistent scan, 4-CTA cluster per batch row, register-resident
//          weights (R8 structure). Cross-CTA h/rh broadcast via st.async +
//          transaction mbarriers (expect_tx/complete_tx) — no cluster.sync,
//          no spin loops, no per-thread release arrives in the loop.

#define BATCH_ 32
#define T_     2048

__device__ float g_pre[(size_t)BATCH_ * T_ * 768];

// ---------------------------------------------------------------------------
// Phase 1: fp32 tiled GEMM  [65536,256] x [256,768] -> g_pre (bias folded).
// BM=128, BN=64, BK=16, 256 threads, 8x4 register tile.  (R8 version)
// ---------------------------------------------------------------------------
__global__ __launch_bounds__(256) void gemm_pre_kernel(
    const float* __restrict__ x,
    const float* __restrict__ Wg, const float* __restrict__ bg,
    const float* __restrict__ Wc, const float* __restrict__ bc)
{
    __shared__ float As[16 * 132];
    __shared__ float Bs[16 * 64];

    const int bn  = blockIdx.x;
    const int bm  = blockIdx.y;
    const int tid = threadIdx.x;

    const float* Wp; int ldw, coff; const float* bias;
    if (bn < 8) { Wp = Wg; ldw = 512; coff = bn * 64;        bias = bg + coff; }
    else        { Wp = Wc; ldw = 256; coff = (bn - 8) * 64;  bias = bc + coff; }

    const int tx   = tid & 15;
    const int ty   = tid >> 4;
    const int arow = tid >> 2;
    const int acol = (tid & 3) * 4;
    const int brow = tid >> 4;
    const int bcol = (tid & 15) * 4;

    const float* Ag = x + (size_t)(bm * 128) * 256;

    float acc[8][4];
#pragma unroll
    for (int i = 0; i < 8; ++i)
#pragma unroll
        for (int j = 0; j < 4; ++j) acc[i][j] = 0.f;

    for (int kt = 0; kt < 256; kt += 16) {
        float4 a0 = *(const float4*)(Ag + (size_t)arow * 256 + kt + acol);
        float4 a1 = *(const float4*)(Ag + (size_t)(arow + 64) * 256 + kt + acol);
        float4 b0 = *(const float4*)(Wp + (size_t)(kt + brow) * ldw + coff + bcol);

        As[(acol + 0) * 132 + arow]      = a0.x;
        As[(acol + 1) * 132 + arow]      = a0.y;
        As[(acol + 2) * 132 + arow]      = a0.z;
        As[(acol + 3) * 132 + arow]      = a0.w;
        As[(acol + 0) * 132 + arow + 64] = a1.x;
        As[(acol + 1) * 132 + arow + 64] = a1.y;
        As[(acol + 2) * 132 + arow + 64] = a1.z;
        As[(acol + 3) * 132 + arow + 64] = a1.w;
        *(float4*)&Bs[brow * 64 + bcol] = b0;
        __syncthreads();

#pragma unroll
        for (int k = 0; k < 16; ++k) {
            float4 av0 = *(const float4*)&As[k * 132 + ty * 8];
            float4 av1 = *(const float4*)&As[k * 132 + ty * 8 + 4];
            float4 bv  = *(const float4*)&Bs[k * 64 + tx * 4];
            float am[8] = {av0.x, av0.y, av0.z, av0.w,
                           av1.x, av1.y, av1.z, av1.w};
#pragma unroll
            for (int i = 0; i < 8; ++i) {
                acc[i][0] += am[i] * bv.x;
                acc[i][1] += am[i] * bv.y;
                acc[i][2] += am[i] * bv.z;
                acc[i][3] += am[i] * bv.w;
            }
        }
        __syncthreads();
    }

    float4 bb = *(const float4*)(bias + tx * 4);
    float* Og = g_pre + (size_t)(bm * 128) * 768 + bn * 64;
#pragma unroll
    for (int i = 0; i < 8; ++i) {
        float4 o;
        o.x = acc[i][0] + bb.x;
        o.y = acc[i][1] + bb.y;
        o.z = acc[i][2] + bb.z;
        o.w = acc[i][3] + bb.w;
        *(float4*)(Og + (size_t)(ty * 8 + i) * 768 + tx * 4) = o;
    }
}

// ---------------------------------------------------------------------------
// Phase 2 helpers
// ---------------------------------------------------------------------------
__device__ __forceinline__ void cluster_sync_() {
    asm volatile("barrier.cluster.arrive.aligned;" ::: "memory");
    asm volatile("barrier.cluster.wait.aligned;" ::: "memory");
}
__device__ __forceinline__ uint32_t smem_u32_(const void* p) {
    uint32_t a;
    asm("{ .reg .u64 t; cvta.to.shared.u64 t, %1; cvt.u32.u64 %0, t; }"
        : "=r"(a) : "l"(p));
    return a;
}
__device__ __forceinline__ uint32_t mapa_(uint32_t laddr, int rk) {
    uint32_t ra;
    asm("mapa.shared::cluster.u32 %0, %1, %2;" : "=r"(ra) : "r"(laddr), "r"(rk));
    return ra;
}
__device__ __forceinline__ void mbar_init_(uint32_t laddr, uint32_t cnt) {
    asm volatile("mbarrier.init.shared.b64 [%0], %1;" :: "r"(laddr), "r"(cnt) : "memory");
}
__device__ __forceinline__ void mbar_expect_tx_(uint32_t laddr, uint32_t bytes) {
    asm volatile("mbarrier.arrive.expect_tx.shared.b64 _, [%0], %1;"
                 :: "r"(laddr), "r"(bytes) : "memory");
}
// remote smem store with HW transaction tracking on the target CTA's mbarrier
__device__ __forceinline__ void st_async_f32_(uint32_t raddr, float v, uint32_t rmbar) {
    asm volatile("st.async.shared::cluster.mbarrier::complete_tx::bytes.f32 [%0], %1, [%2];"
                 :: "r"(raddr), "f"(v), "r"(rmbar) : "memory");
}
__device__ __forceinline__ void mbar_wait_par_(uint32_t laddr, uint32_t parity) {
    asm volatile(
        "{\n\t.reg .pred P;\n\t"
        "WL%=:\n\t"
        "mbarrier.try_wait.parity.acquire.cta.shared::cta.b64 P, [%0], %1, 0x989680;\n\t"
        "@P bra.uni WD%=;\n\t"
        "bra.uni WL%=;\n\t"
        "WD%=:\n\t}"
        :: "r"(laddr), "r"(parity) : "memory");
}
__device__ __forceinline__ uint64_t pack2_(float a, float b) {
    uint64_t r;
    asm("mov.b64 %0, {%1, %2};" : "=l"(r) : "f"(a), "f"(b));
    return r;
}
__device__ __forceinline__ void unpack2_(uint64_t v, float& a, float& b) {
    asm("mov.b64 {%0, %1}, %2;" : "=f"(a), "=f"(b) : "l"(v));
}
__device__ __forceinline__ void fma2_(uint64_t& d, uint64_t a, uint64_t b) {
    asm("fma.rn.f32x2 %0, %1, %2, %0;" : "+l"(d) : "l"(a), "l"(b));
}
__device__ __forceinline__ void lds_v2u64_(uint32_t addr, uint64_t& a, uint64_t& b) {
    asm volatile("ld.shared.v2.u64 {%0, %1}, [%2];" : "=l"(a), "=l"(b) : "r"(addr));
}

// ---------------------------------------------------------------------------
// Phase 2: grid = 128 CTAs, cluster(4,1,1), 512 threads (R8 mapping).
// Warp w: gate slice sg=w&3 (64 k), gate col (w>>2)*32+lane (0..127);
//         cand slice sc=w&7 (32 k), cand col (w>>3)*32+lane (0..63).
// Exchange: producers (tid<64) st.async their rh / h element to all 4 CTAs;
// each CTA's tx-mbarrier expects 1024 bytes per phase; all threads try_wait.
// ---------------------------------------------------------------------------
__global__ void __cluster_dims__(4, 1, 1) __launch_bounds__(512, 1)
gru_rec_kernel(const float* __restrict__ Wg, const float* __restrict__ Wc,
               const float* __restrict__ h0, float* __restrict__ out)
{
    __shared__ __align__(16) float hbuf[256];
    __shared__ __align__(16) float rhbuf[256];
    __shared__ float ubuf[64];
    __shared__ float pbuf[2 * 192];
    __shared__ __align__(16) float redA[128 * 4];   // [col][slice]
    __shared__ __align__(16) float redB[64 * 8];    // [col][slice]
    __shared__ __align__(8) uint64_t mbar_rh;
    __shared__ __align__(8) uint64_t mbar_h;

    const int tid  = threadIdx.x;
    const int w    = tid >> 5;
    const int lane = tid & 31;
    uint32_t rank;
    asm("mov.u32 %0, %%cluster_ctarank;" : "=r"(rank));
    const int b = blockIdx.x >> 2;

    const int sg  = w & 3;
    const int col = (w >> 2) * 32 + lane;          // 0..127
    const int gcol = (col < 64) ? (int)(rank * 64 + col)
                                : (int)(256 + rank * 64 + (col - 64));
    const int sc  = w & 7;
    const int cc  = (w >> 3) * 32 + lane;          // 0..63
    const int ccol = rank * 64 + cc;

    // register-resident weights (R8 layout)
    uint64_t wg2[32];
#pragma unroll
    for (int j = 0; j < 16; ++j) {
        int k = sg * 64 + j * 4;
        float w0 = Wg[(size_t)(256 + k + 0) * 512 + gcol];
        float w1 = Wg[(size_t)(256 + k + 1) * 512 + gcol];
        float w2 = Wg[(size_t)(256 + k + 2) * 512 + gcol];
        float w3 = Wg[(size_t)(256 + k + 3) * 512 + gcol];
        wg2[2 * j]     = pack2_(w0, w1);
        wg2[2 * j + 1] = pack2_(w2, w3);
    }
    uint64_t wc2[16];
#pragma unroll
    for (int j = 0; j < 8; ++j) {
        int k = sc * 32 + j * 4;
        float w0 = Wc[(size_t)(256 + k + 0) * 256 + ccol];
        float w1 = Wc[(size_t)(256 + k + 1) * 256 + ccol];
        float w2 = Wc[(size_t)(256 + k + 2) * 256 + ccol];
        float w3 = Wc[(size_t)(256 + k + 3) * 256 + ccol];
        wc2[2 * j]     = pack2_(w0, w1);
        wc2[2 * j + 1] = pack2_(w2, w3);
    }

    for (int i = tid; i < 256; i += 512) hbuf[i] = h0[b * 256 + i];

    const uint32_t mrh_l = smem_u32_(&mbar_rh);
    const uint32_t mh_l  = smem_u32_(&mbar_h);
    if (tid == 0) {
        mbar_init_(mrh_l, 1);     // 1 arrival: the local expect_tx post
        mbar_init_(mh_l, 1);
        mbar_expect_tx_(mrh_l, 1024);   // arm rh phase 0 before anyone stores
    }

    int preidx = 0;
    if      (tid < 64)  preidx = rank * 64 + tid;
    else if (tid < 128) preidx = 256 + rank * 64 + (tid - 64);
    else if (tid < 192) preidx = 512 + rank * 64 + (tid - 128);

    const float* prow = g_pre + (size_t)b * T_ * 768;
    float*       orow = out   + (size_t)b * T_ * 256;

    if (tid < 192) pbuf[tid] = prow[preidx];
    __syncthreads();
    cluster_sync_();   // mbar init + arming + hbuf visible cluster-wide

    const uint32_t hb   = smem_u32_(hbuf);
    const uint32_t rhb  = smem_u32_(rhbuf);
    const uint32_t ha_g = hb  + sg * 256;
    const uint32_t ra_c = rhb + sc * 128;

    // remote data addresses for producers (tid<64); remote mbar addresses
    // derived by constant delta (mapa preserves intra-CTA offsets).
    uint32_t rh_rem[4], h_rem[4];
    {
        uint32_t e = (rank * 64 + (tid & 63)) * 4;
#pragma unroll
        for (int rk = 0; rk < 4; ++rk) {
            rh_rem[rk] = mapa_(rhb + e, rk);
            h_rem[rk]  = mapa_(hb + e,  rk);
        }
    }
    const uint32_t d_rh2m = mrh_l - (rhb + (rank * 64 + (tid & 63)) * 4);
    const uint32_t d_h2m  = mh_l  - (hb  + (rank * 64 + (tid & 63)) * 4);

    for (int t = 0; t < T_; ++t) {
        const int cur = (t & 1) * 192, nxt = ((t & 1) ^ 1) * 192;
        const uint32_t par = (uint32_t)(t & 1);

        // arm h phase t (before gate sync -> before our rh stores -> before
        // any remote h store can target us)
        if (tid == 0) mbar_expect_tx_(mh_l, 1024);

        float pre_next = 0.f;
        if (tid < 192 && t + 1 < T_)
            pre_next = prow[(size_t)(t + 1) * 768 + preidx];

        // ---- gates partial: h[sg*64..+64) . wg ----
        {
            uint64_t a0 = 0, a1 = 0;
#pragma unroll
            for (int j = 0; j < 16; ++j) {
                uint64_t h01, h23;
                lds_v2u64_(ha_g + j * 16, h01, h23);
                fma2_(a0, wg2[2 * j],     h01);
                fma2_(a1, wg2[2 * j + 1], h23);
            }
            float x0, x1, y0, y1;
            unpack2_(a0, x0, x1);
            unpack2_(a1, y0, y1);
            redA[col * 4 + sg] = (x0 + x1) + (y0 + y1);
        }
        __syncthreads();

        // ---- gate finalize: 128 threads, one column each ----
        if (tid < 128) {
            float4 p4 = *(const float4*)&redA[tid * 4];
            float s = p4.x + p4.y + p4.z + p4.w + pbuf[cur + tid];
            float g = 1.f / (1.f + __expf(-s));
            if (tid < 64) {
                float rh = g * hbuf[rank * 64 + tid];
#pragma unroll
                for (int rk = 0; rk < 4; ++rk)
                    st_async_f32_(rh_rem[rk], rh, rh_rem[rk] + d_rh2m);
            } else {
                ubuf[tid - 64] = g;
            }
        }
        mbar_wait_par_(mrh_l, par);          // rhbuf complete (1024B + arm)
        if (tid == 0) mbar_expect_tx_(mrh_l, 1024);   // arm rh phase t+1

        // ---- candidate partial: rh[sc*32..+32) . wc ----
        {
            uint64_t c0 = 0, c1 = 0;
#pragma unroll
            for (int j = 0; j < 8; ++j) {
                uint64_t h01, h23;
                lds_v2u64_(ra_c + j * 16, h01, h23);
                fma2_(c0, wc2[2 * j],     h01);
                fma2_(c1, wc2[2 * j + 1], h23);
            }
            float x0, x1, y0, y1;
            unpack2_(c0, x0, x1);
            unpack2_(c1, y0, y1);
            redB[cc * 8 + sc] = (x0 + x1) + (y0 + y1);
        }
        __syncthreads();   // redB/ubuf ready; also orders tid0's rh re-arm

        // ---- h update: 64 threads, one column each ----
        if (tid < 64) {
            float4 p0 = *(const float4*)&redB[tid * 8];
            float4 p1 = *(const float4*)&redB[tid * 8 + 4];
            float s = ((p0.x + p0.y) + (p0.z + p0.w))
                    + ((p1.x + p1.y) + (p1.z + p1.w))
                    + pbuf[cur + 128 + tid];
            float c  = tanhf(s);
            float u  = ubuf[tid];
            float hn = u * hbuf[rank * 64 + tid] + (1.f - u) * c;
            orow[(size_t)t * 256 + rank * 64 + tid] = hn;
            if (t + 1 < T_) {
#pragma unroll
                for (int rk = 0; rk < 4; ++rk)
                    st_async_f32_(h_rem[rk], hn, h_rem[rk] + d_h2m);
            }
        }
        if (tid < 192) pbuf[nxt + tid] = pre_next;
        if (t + 1 < T_) mbar_wait_par_(mh_l, par);   // hbuf complete
    }
}

// ---------------------------------------------------------------------------
extern "C" void kernel_launch(void* const* d_in, const int* in_sizes, int n_in,
                              void* d_out, int out_size) {
    const float* x  = (const float*)d_in[0];
    const float* h0 = (const float*)d_in[1];
    const float* Wg = (const float*)d_in[2];
    const float* bg = (const float*)d_in[3];
    const float* Wc = (const float*)d_in[4];
    const float* bc = (const float*)d_in[5];
    float* out = (float*)d_out;

    dim3 g1(12, 512);
    gemm_pre_kernel<<<g1, 256>>>(x, Wg, bg, Wc, bc);
    gru_rec_kernel<<<128, 512>>>(Wg, Wc, h0, out);
}

// round 13
// speedup vs baseline: 2.2888x; 1.0655x over previous
#include <cuda_runtime.h>
#include <cstdint>

// DynamicGRU: B=32, T=2048, D=256, N=256
// Phase 1: PRE = x @ [W_g[:256,:] | W_c[:256,:]] + bias — tf32 mma.sync GEMM.
// Phase 2: persistent scan, 4-CTA cluster per batch row, register-resident
//          weights, st.async + transaction-mbarrier h/rh exchange (R12).

#define BATCH_ 32
#define T_     2048

__device__ float g_pre[(size_t)BATCH_ * T_ * 768];

// ---------------------------------------------------------------------------
// Phase 1 helpers
// ---------------------------------------------------------------------------
__device__ __forceinline__ float tf32_(float x) {
    float r;
    asm("cvt.rna.tf32.f32 %0, %1;" : "=f"(r) : "f"(x));
    return r;
}
__device__ __forceinline__ void mma_tf32_(float* d, const uint32_t* a, const uint32_t* b) {
    asm volatile(
        "mma.sync.aligned.m16n8k8.row.col.f32.tf32.tf32.f32 "
        "{%0,%1,%2,%3}, {%4,%5,%6,%7}, {%8,%9}, {%0,%1,%2,%3};"
        : "+f"(d[0]), "+f"(d[1]), "+f"(d[2]), "+f"(d[3])
        : "r"(a[0]), "r"(a[1]), "r"(a[2]), "r"(a[3]), "r"(b[0]), "r"(b[1]));
}

// ---------------------------------------------------------------------------
// Phase 1: tf32 GEMM  [65536,256] x [256,768] -> g_pre (bias folded).
// BM=128, BN=64, BK=32, 256 threads = 8 warps (2x4), warp tile 64x16.
// A smem padded to 36 floats/row, B to 72: fragment LDS conflict-free.
// ---------------------------------------------------------------------------
__global__ __launch_bounds__(256) void gemm_pre_tf32_kernel(
    const float* __restrict__ x,
    const float* __restrict__ Wg, const float* __restrict__ bg,
    const float* __restrict__ Wc, const float* __restrict__ bc)
{
    __shared__ __align__(16) float As[128][36];
    __shared__ __align__(16) float Bs[32][72];

    const int bn  = blockIdx.x;   // 0..11 (64-wide col block)
    const int bm  = blockIdx.y;   // 0..511
    const int tid = threadIdx.x;
    const int ww  = tid >> 5;     // warp 0..7
    const int lane = tid & 31;
    const int wm  = ww >> 2;      // 0..1  (64-row half)
    const int wn  = ww & 3;       // 0..3  (16-col slice)
    const int lr  = lane >> 2;    // 0..7
    const int lq  = lane & 3;     // 0..3

    const float* Wp; int ldw, coff; const float* bias;
    if (bn < 8) { Wp = Wg; ldw = 512; coff = bn * 64;        bias = bg + coff; }
    else        { Wp = Wc; ldw = 256; coff = (bn - 8) * 64;  bias = bc + coff; }

    const float* Ag = x + (size_t)(bm * 128) * 256;

    // gmem->smem mapping
    const int arow = tid >> 1;            // 0..127
    const int akq  = (tid & 1) * 16;      // 0 or 16
    const int brow = tid >> 3;            // 0..31
    const int bnq  = (tid & 7) * 8;       // 0..56

    float acc[4][2][4];
#pragma unroll
    for (int mt = 0; mt < 4; ++mt)
#pragma unroll
        for (int nt = 0; nt < 2; ++nt)
#pragma unroll
            for (int i = 0; i < 4; ++i) acc[mt][nt][i] = 0.f;

    for (int kt = 0; kt < 256; kt += 32) {
        // load + tf32-convert A tile [128][32]
#pragma unroll
        for (int j = 0; j < 4; ++j) {
            float4 v = *(const float4*)(Ag + (size_t)arow * 256 + kt + akq + j * 4);
            As[arow][akq + j * 4 + 0] = tf32_(v.x);
            As[arow][akq + j * 4 + 1] = tf32_(v.y);
            As[arow][akq + j * 4 + 2] = tf32_(v.z);
            As[arow][akq + j * 4 + 3] = tf32_(v.w);
        }
        // load + tf32-convert B tile [32][64]
#pragma unroll
        for (int j = 0; j < 2; ++j) {
            float4 v = *(const float4*)(Wp + (size_t)(kt + brow) * ldw + coff + bnq + j * 4);
            Bs[brow][bnq + j * 4 + 0] = tf32_(v.x);
            Bs[brow][bnq + j * 4 + 1] = tf32_(v.y);
            Bs[brow][bnq + j * 4 + 2] = tf32_(v.z);
            Bs[brow][bnq + j * 4 + 3] = tf32_(v.w);
        }
        __syncthreads();

#pragma unroll
        for (int ks = 0; ks < 4; ++ks) {
            const int k0 = ks * 8 + lq;
            uint32_t af[4][4];
#pragma unroll
            for (int mt = 0; mt < 4; ++mt) {
                const int r0 = wm * 64 + mt * 16 + lr;
                af[mt][0] = __float_as_uint(As[r0][k0]);
                af[mt][1] = __float_as_uint(As[r0 + 8][k0]);
                af[mt][2] = __float_as_uint(As[r0][k0 + 4]);
                af[mt][3] = __float_as_uint(As[r0 + 8][k0 + 4]);
            }
            uint32_t bf[2][2];
#pragma unroll
            for (int nt = 0; nt < 2; ++nt) {
                const int c0 = wn * 16 + nt * 8 + lr;
                bf[nt][0] = __float_as_uint(Bs[k0][c0]);
                bf[nt][1] = __float_as_uint(Bs[k0 + 4][c0]);
            }
#pragma unroll
            for (int mt = 0; mt < 4; ++mt)
#pragma unroll
                for (int nt = 0; nt < 2; ++nt)
                    mma_tf32_(acc[mt][nt], af[mt], bf[nt]);
        }
        __syncthreads();
    }

    // epilogue: bias + store
    float* Og = g_pre + (size_t)(bm * 128) * 768 + bn * 64;
#pragma unroll
    for (int mt = 0; mt < 4; ++mt) {
#pragma unroll
        for (int nt = 0; nt < 2; ++nt) {
            const int row = wm * 64 + mt * 16 + lr;
            const int cl  = wn * 16 + nt * 8 + 2 * lq;
            float b0 = bias[cl], b1 = bias[cl + 1];
            float* d0 = Og + (size_t)row * 768 + cl;
            float* d1 = Og + (size_t)(row + 8) * 768 + cl;
            d0[0] = acc[mt][nt][0] + b0;
            d0[1] = acc[mt][nt][1] + b1;
            d1[0] = acc[mt][nt][2] + b0;
            d1[1] = acc[mt][nt][3] + b1;
        }
    }
}

// ---------------------------------------------------------------------------
// Phase 2 helpers (identical to R12)
// ---------------------------------------------------------------------------
__device__ __forceinline__ void cluster_sync_() {
    asm volatile("barrier.cluster.arrive.aligned;" ::: "memory");
    asm volatile("barrier.cluster.wait.aligned;" ::: "memory");
}
__device__ __forceinline__ uint32_t smem_u32_(const void* p) {
    uint32_t a;
    asm("{ .reg .u64 t; cvta.to.shared.u64 t, %1; cvt.u32.u64 %0, t; }"
        : "=r"(a) : "l"(p));
    return a;
}
__device__ __forceinline__ uint32_t mapa_(uint32_t laddr, int rk) {
    uint32_t ra;
    asm("mapa.shared::cluster.u32 %0, %1, %2;" : "=r"(ra) : "r"(laddr), "r"(rk));
    return ra;
}
__device__ __forceinline__ void mbar_init_(uint32_t laddr, uint32_t cnt) {
    asm volatile("mbarrier.init.shared.b64 [%0], %1;" :: "r"(laddr), "r"(cnt) : "memory");
}
__device__ __forceinline__ void mbar_expect_tx_(uint32_t laddr, uint32_t bytes) {
    asm volatile("mbarrier.arrive.expect_tx.shared.b64 _, [%0], %1;"
                 :: "r"(laddr), "r"(bytes) : "memory");
}
__device__ __forceinline__ void st_async_f32_(uint32_t raddr, float v, uint32_t rmbar) {
    asm volatile("st.async.shared::cluster.mbarrier::complete_tx::bytes.f32 [%0], %1, [%2];"
                 :: "r"(raddr), "f"(v), "r"(rmbar) : "memory");
}
__device__ __forceinline__ void mbar_wait_par_(uint32_t laddr, uint32_t parity) {
    asm volatile(
        "{\n\t.reg .pred P;\n\t"
        "WL%=:\n\t"
        "mbarrier.try_wait.parity.acquire.cta.shared::cta.b64 P, [%0], %1, 0x989680;\n\t"
        "@P bra.uni WD%=;\n\t"
        "bra.uni WL%=;\n\t"
        "WD%=:\n\t}"
        :: "r"(laddr), "r"(parity) : "memory");
}
__device__ __forceinline__ uint64_t pack2_(float a, float b) {
    uint64_t r;
    asm("mov.b64 %0, {%1, %2};" : "=l"(r) : "f"(a), "f"(b));
    return r;
}
__device__ __forceinline__ void unpack2_(uint64_t v, float& a, float& b) {
    asm("mov.b64 {%0, %1}, %2;" : "=f"(a), "=f"(b) : "l"(v));
}
__device__ __forceinline__ void fma2_(uint64_t& d, uint64_t a, uint64_t b) {
    asm("fma.rn.f32x2 %0, %1, %2, %0;" : "+l"(d) : "l"(a), "l"(b));
}
__device__ __forceinline__ void lds_v2u64_(uint32_t addr, uint64_t& a, uint64_t& b) {
    asm volatile("ld.shared.v2.u64 {%0, %1}, [%2];" : "=l"(a), "=l"(b) : "r"(addr));
}

// ---------------------------------------------------------------------------
// Phase 2: grid = 128 CTAs, cluster(4,1,1), 512 threads (R12, unchanged).
// ---------------------------------------------------------------------------
__global__ void __cluster_dims__(4, 1, 1) __launch_bounds__(512, 1)
gru_rec_kernel(const float* __restrict__ Wg, const float* __restrict__ Wc,
               const float* __restrict__ h0, float* __restrict__ out)
{
    __shared__ __align__(16) float hbuf[256];
    __shared__ __align__(16) float rhbuf[256];
    __shared__ float ubuf[64];
    __shared__ float pbuf[2 * 192];
    __shared__ __align__(16) float redA[128 * 4];
    __shared__ __align__(16) float redB[64 * 8];
    __shared__ __align__(8) uint64_t mbar_rh;
    __shared__ __align__(8) uint64_t mbar_h;

    const int tid  = threadIdx.x;
    const int w    = tid >> 5;
    const int lane = tid & 31;
    uint32_t rank;
    asm("mov.u32 %0, %%cluster_ctarank;" : "=r"(rank));
    const int b = blockIdx.x >> 2;

    const int sg  = w & 3;
    const int col = (w >> 2) * 32 + lane;
    const int gcol = (col < 64) ? (int)(rank * 64 + col)
                                : (int)(256 + rank * 64 + (col - 64));
    const int sc  = w & 7;
    const int cc  = (w >> 3) * 32 + lane;
    const int ccol = rank * 64 + cc;

    uint64_t wg2[32];
#pragma unroll
    for (int j = 0; j < 16; ++j) {
        int k = sg * 64 + j * 4;
        float w0 = Wg[(size_t)(256 + k + 0) * 512 + gcol];
        float w1 = Wg[(size_t)(256 + k + 1) * 512 + gcol];
        float w2 = Wg[(size_t)(256 + k + 2) * 512 + gcol];
        float w3 = Wg[(size_t)(256 + k + 3) * 512 + gcol];
        wg2[2 * j]     = pack2_(w0, w1);
        wg2[2 * j + 1] = pack2_(w2, w3);
    }
    uint64_t wc2[16];
#pragma unroll
    for (int j = 0; j < 8; ++j) {
        int k = sc * 32 + j * 4;
        float w0 = Wc[(size_t)(256 + k + 0) * 256 + ccol];
        float w1 = Wc[(size_t)(256 + k + 1) * 256 + ccol];
        float w2 = Wc[(size_t)(256 + k + 2) * 256 + ccol];
        float w3 = Wc[(size_t)(256 + k + 3) * 256 + ccol];
        wc2[2 * j]     = pack2_(w0, w1);
        wc2[2 * j + 1] = pack2_(w2, w3);
    }

    for (int i = tid; i < 256; i += 512) hbuf[i] = h0[b * 256 + i];

    const uint32_t mrh_l = smem_u32_(&mbar_rh);
    const uint32_t mh_l  = smem_u32_(&mbar_h);
    if (tid == 0) {
        mbar_init_(mrh_l, 1);
        mbar_init_(mh_l, 1);
        mbar_expect_tx_(mrh_l, 1024);
    }

    int preidx = 0;
    if      (tid < 64)  preidx = rank * 64 + tid;
    else if (tid < 128) preidx = 256 + rank * 64 + (tid - 64);
    else if (tid < 192) preidx = 512 + rank * 64 + (tid - 128);

    const float* prow = g_pre + (size_t)b * T_ * 768;
    float*       orow = out   + (size_t)b * T_ * 256;

    if (tid < 192) pbuf[tid] = prow[preidx];
    __syncthreads();
    cluster_sync_();

    const uint32_t hb   = smem_u32_(hbuf);
    const uint32_t rhb  = smem_u32_(rhbuf);
    const uint32_t ha_g = hb  + sg * 256;
    const uint32_t ra_c = rhb + sc * 128;

    uint32_t rh_rem[4], h_rem[4];
    {
        uint32_t e = (rank * 64 + (tid & 63)) * 4;
#pragma unroll
        for (int rk = 0; rk < 4; ++rk) {
            rh_rem[rk] = mapa_(rhb + e, rk);
            h_rem[rk]  = mapa_(hb + e,  rk);
        }
    }
    const uint32_t d_rh2m = mrh_l - (rhb + (rank * 64 + (tid & 63)) * 4);
    const uint32_t d_h2m  = mh_l  - (hb  + (rank * 64 + (tid & 63)) * 4);

    for (int t = 0; t < T_; ++t) {
        const int cur = (t & 1) * 192, nxt = ((t & 1) ^ 1) * 192;
        const uint32_t par = (uint32_t)(t & 1);

        if (tid == 0) mbar_expect_tx_(mh_l, 1024);

        float pre_next = 0.f;
        if (tid < 192 && t + 1 < T_)
            pre_next = prow[(size_t)(t + 1) * 768 + preidx];

        {
            uint64_t a0 = 0, a1 = 0;
#pragma unroll
            for (int j = 0; j < 16; ++j) {
                uint64_t h01, h23;
                lds_v2u64_(ha_g + j * 16, h01, h23);
                fma2_(a0, wg2[2 * j],     h01);
                fma2_(a1, wg2[2 * j + 1], h23);
            }
            float x0, x1, y0, y1;
            unpack2_(a0, x0, x1);
            unpack2_(a1, y0, y1);
            redA[col * 4 + sg] = (x0 + x1) + (y0 + y1);
        }
        __syncthreads();

        if (tid < 128) {
            float4 p4 = *(const float4*)&redA[tid * 4];
            float s = p4.x + p4.y + p4.z + p4.w + pbuf[cur + tid];
            float g = 1.f / (1.f + __expf(-s));
            if (tid < 64) {
                float rh = g * hbuf[rank * 64 + tid];
#pragma unroll
                for (int rk = 0; rk < 4; ++rk)
                    st_async_f32_(rh_rem[rk], rh, rh_rem[rk] + d_rh2m);
            } else {
                ubuf[tid - 64] = g;
            }
        }
        mbar_wait_par_(mrh_l, par);
        if (tid == 0) mbar_expect_tx_(mrh_l, 1024);

        {
            uint64_t c0 = 0, c1 = 0;
#pragma unroll
            for (int j = 0; j < 8; ++j) {
                uint64_t h01, h23;
                lds_v2u64_(ra_c + j * 16, h01, h23);
                fma2_(c0, wc2[2 * j],     h01);
                fma2_(c1, wc2[2 * j + 1], h23);
            }
            float x0, x1, y0, y1;
            unpack2_(c0, x0, x1);
            unpack2_(c1, y0, y1);
            redB[cc * 8 + sc] = (x0 + x1) + (y0 + y1);
        }
        __syncthreads();

        if (tid < 64) {
            float4 p0 = *(const float4*)&redB[tid * 8];
            float4 p1 = *(const float4*)&redB[tid * 8 + 4];
            float s = ((p0.x + p0.y) + (p0.z + p0.w))
                    + ((p1.x + p1.y) + (p1.z + p1.w))
                    + pbuf[cur + 128 + tid];
            float c  = tanhf(s);
            float u  = ubuf[tid];
            float hn = u * hbuf[rank * 64 + tid] + (1.f - u) * c;
            orow[(size_t)t * 256 + rank * 64 + tid] = hn;
            if (t + 1 < T_) {
#pragma unroll
                for (int rk = 0; rk < 4; ++rk)
                    st_async_f32_(h_rem[rk], hn, h_rem[rk] + d_h2m);
            }
        }
        if (tid < 192) pbuf[nxt + tid] = pre_next;
        if (t + 1 < T_) mbar_wait_par_(mh_l, par);
    }
}

// ---------------------------------------------------------------------------
extern "C" void kernel_launch(void* const* d_in, const int* in_sizes, int n_in,
                              void* d_out, int out_size) {
    const float* x  = (const float*)d_in[0];
    const float* h0 = (const float*)d_in[1];
    const float* Wg = (const float*)d_in[2];
    const float* bg = (const float*)d_in[3];
    const float* Wc = (const float*)d_in[4];
    const float* bc = (const float*)d_in[5];
    float* out = (float*)d_out;

    dim3 g1(12, 512);
    gemm_pre_tf32_kernel<<<g1, 256>>>(x, Wg, bg, Wc, bc);
    gru_rec_kernel<<<128, 512>>>(Wg, Wc, h0, out);
}